// round 11
// baseline (speedup 1.0000x reference)
#include <cuda_runtime.h>
#include <math.h>

#define N_NODES 100000
#define N_EDGES 1600000
#define IN_DIM  64
#define EMB     128
#define ED      32

#define SCAN_BLK 512
#define NBLK ((N_NODES + SCAN_BLK - 1) / SCAN_BLK)   // 196

typedef unsigned long long u64;

__device__ __forceinline__ u64 pack2(float x, float y) {
    u64 r; asm("mov.b64 %0, {%1, %2};" : "=l"(r) : "f"(x), "f"(y)); return r;
}
__device__ __forceinline__ void unpack2(u64 v, float& x, float& y) {
    asm("mov.b64 {%0, %1}, %2;" : "=f"(x), "=f"(y) : "l"(v));
}
__device__ __forceinline__ u64 ffma2(u64 a, u64 b, u64 c) {
    u64 d; asm("fma.rn.f32x2 %0, %1, %2, %3;" : "=l"(d) : "l"(a), "l"(b), "l"(c));
    return d;
}
__device__ __forceinline__ u64 fadd2(u64 a, u64 b) {
    u64 d; asm("add.rn.f32x2 %0, %1, %2;" : "=l"(d) : "l"(a), "l"(b));
    return d;
}
__device__ __forceinline__ unsigned smem_u32(const void* p) {
    return (unsigned)__cvta_generic_to_shared(p);
}
__device__ __forceinline__ void cp16(void* smem, const void* gmem) {
    asm volatile("cp.async.ca.shared.global [%0], [%1], 16;"
                 :: "r"(smem_u32(smem)), "l"(gmem));
}

__device__ float g_agg[2][(size_t)N_NODES * IN_DIM];
__device__ float g_t[2][(size_t)N_NODES * EMB];     // holds 0.5*gelu(...) (ALPHA folded)

// CSR scratch
__device__ int  g_deg[2][N_NODES];
__device__ int  g_cur[2][N_NODES];
__device__ int  g_off[2][N_NODES + 1];
__device__ int  g_partial[2][NBLK];
__device__ int  g_pscan[2][NBLK];
__device__ int2 g_elist2[2][N_EDGES];   // {edge id, gather node}

// ---------------------------------------------------------------------------
// CSR build
// ---------------------------------------------------------------------------
__global__ void zero_deg_kernel() {
    int i = blockIdx.x * blockDim.x + threadIdx.x;
    if (i < N_NODES) { g_deg[0][i] = 0; g_deg[1][i] = 0; }
}

__global__ void count_kernel(const int* __restrict__ ei) {
    int e = blockIdx.x * blockDim.x + threadIdx.x;
    if (e < N_EDGES) {
        int s = ei[e];
        int d = ei[N_EDGES + e];
        atomicAdd(&g_deg[0][d], 1);
        atomicAdd(&g_deg[1][s], 1);
    }
}

__global__ void scan1_kernel() {
    const int dir = blockIdx.y;
    __shared__ int sred[SCAN_BLK];
    int i = blockIdx.x * SCAN_BLK + threadIdx.x;
    sred[threadIdx.x] = (i < N_NODES) ? g_deg[dir][i] : 0;
    __syncthreads();
    for (int ofs = SCAN_BLK / 2; ofs > 0; ofs >>= 1) {
        if (threadIdx.x < ofs) sred[threadIdx.x] += sred[threadIdx.x + ofs];
        __syncthreads();
    }
    if (threadIdx.x == 0) g_partial[dir][blockIdx.x] = sred[0];
}

__global__ void scan2_kernel() {
    const int dir = blockIdx.y;
    __shared__ int sb[2][256];
    int t = threadIdx.x;
    int v = (t < NBLK) ? g_partial[dir][t] : 0;
    sb[0][t] = v;
    __syncthreads();
    int cur = 0;
#pragma unroll
    for (int ofs = 1; ofs < 256; ofs <<= 1) {
        int val = sb[cur][t];
        if (t >= ofs) val += sb[cur][t - ofs];
        sb[cur ^ 1][t] = val;
        __syncthreads();
        cur ^= 1;
    }
    if (t < NBLK) g_pscan[dir][t] = sb[cur][t] - v;
}

__global__ void scan3_kernel() {
    const int dir = blockIdx.y;
    __shared__ int sb[2][SCAN_BLK];
    int t = threadIdx.x;
    int i = blockIdx.x * SCAN_BLK + t;
    int v = (i < N_NODES) ? g_deg[dir][i] : 0;
    sb[0][t] = v;
    __syncthreads();
    int cur = 0;
#pragma unroll
    for (int ofs = 1; ofs < SCAN_BLK; ofs <<= 1) {
        int val = sb[cur][t];
        if (t >= ofs) val += sb[cur][t - ofs];
        sb[cur ^ 1][t] = val;
        __syncthreads();
        cur ^= 1;
    }
    int incl = sb[cur][t];
    int base = g_pscan[dir][blockIdx.x];
    if (i < N_NODES) {
        int excl = base + incl - v;
        g_off[dir][i] = excl;
        g_cur[dir][i] = excl;
        if (i == N_NODES - 1) g_off[dir][N_NODES] = base + incl;
    }
}

__global__ void fill_kernel(const int* __restrict__ ei) {
    int e = blockIdx.x * blockDim.x + threadIdx.x;
    if (e < N_EDGES) {
        int s = ei[e];
        int d = ei[N_EDGES + e];
        int p0 = atomicAdd(&g_cur[0][d], 1);
        g_elist2[0][p0] = make_int2(e, s);
        int p1 = atomicAdd(&g_cur[1][s], 1);
        g_elist2[1][p1] = make_int2(e, d);
    }
}

// ---------------------------------------------------------------------------
// Aggregation: warp per node, 4-edge groups, CROSS-NODE software pipeline —
// the next group (even in the next node) is prefetched during compute.
// ---------------------------------------------------------------------------
#define LOAD_GROUP(j0v, endv, XG, EV)                              \
    {                                                              \
        int  jjl[4];                                               \
        int2 ppl[4];                                               \
        _Pragma("unroll")                                          \
        for (int i = 0; i < 4; i++) {                              \
            int jj = (j0v + i < endv) ? (j0v + i) : (j0v);         \
            jjl[i] = min(jj, N_EDGES - 1);                         \
        }                                                          \
        _Pragma("unroll")                                          \
        for (int i = 0; i < 4; i++) ppl[i] = elist[jjl[i]];        \
        _Pragma("unroll")                                          \
        for (int i = 0; i < 4; i++)                                \
            XG[i] = x2[(size_t)ppl[i].y * 32 + lane];              \
        _Pragma("unroll")                                          \
        for (int i = 0; i < 4; i++)                                \
            EV[i] = ea[(size_t)ppl[i].x * 32 + lane];              \
    }

__global__ __launch_bounds__(256, 2) void agg_kernel(
    const float2* __restrict__ x2,        // x as [N_NODES][32] float2
    const float* __restrict__ ea,         // [N_EDGES][32]
    const float2* __restrict__ We_in2,
    const float2* __restrict__ be_in2,
    const float2* __restrict__ We_out2,
    const float2* __restrict__ be_out2)
{
    const int dir  = blockIdx.y;
    const int lane = threadIdx.x & 31;
    const int w    = threadIdx.x >> 5;

    const float2* We2 = dir ? We_out2 : We_in2;
    const float2  biasv = dir ? be_out2[lane] : be_in2[lane];
    const u64 biasP = pack2(biasv.x, biasv.y);
    const int*  off   = g_off[dir];
    const int2* elist = g_elist2[dir];
    float* __restrict__ agg = g_agg[dir];

    u64 wreg2[32];
#pragma unroll
    for (int k = 0; k < 32; k++) {
        float2 wv = We2[k * 32 + lane];
        wreg2[k] = pack2(wv.x, wv.y);
    }

    __shared__ float2 sEaD[8][4][32];   // duplicated pairs {a,a}

    const int S = gridDim.x * 8;
    int n = blockIdx.x * 8 + w;
    if (n >= N_NODES) return;

    int beg = off[n];
    int end = off[n + 1];
    int j0  = beg;
    float2 accN = make_float2(0.f, 0.f);

    float2 xc[4]; float ec[4];
    LOAD_GROUP(j0, end, xc, ec);

    while (n < N_NODES) {
        // ---- next state (possibly next node) + prefetch ----
        int nn = n, nj0 = j0 + 4, nbeg = beg, nend = end;
        if (nj0 >= end) {
            nn = n + S;
            if (nn < N_NODES) {
                nbeg = off[nn];
                nend = off[nn + 1];
                nj0  = nbeg;
            }
        }
        float2 xn[4]; float en[4];
        if (nn < N_NODES) LOAD_GROUP(nj0, nend, xn, en);

        // ---- compute current group ----
#pragma unroll
        for (int i = 0; i < 4; i++)
            sEaD[w][i][lane] = make_float2(ec[i], ec[i]);
        __syncwarp();

        u64 m[4];
#pragma unroll
        for (int i = 0; i < 4; i++)
            m[i] = fadd2(pack2(xc[i].x, xc[i].y), biasP);

#pragma unroll
        for (int k0 = 0; k0 < 32; k0 += 2) {
#pragma unroll
            for (int i = 0; i < 4; i++) {
                ulonglong2 ap = *(const ulonglong2*)&sEaD[w][i][k0];
                m[i] = ffma2(ap.x, wreg2[k0],     m[i]);
                m[i] = ffma2(ap.y, wreg2[k0 + 1], m[i]);
            }
        }

#pragma unroll
        for (int i = 0; i < 4; i++) {
            float mx, my;
            unpack2(m[i], mx, my);
            mx = fmaxf(mx, 0.f);
            my = fmaxf(my, 0.f);
            if (j0 + i < end) { accN.x += mx; accN.y += my; }
        }
        __syncwarp();

        // ---- node finished? store and reset ----
        if (nn != n) {
            *(float2*)&agg[(size_t)n * 64 + 2 * lane] = accN;
            accN = make_float2(0.f, 0.f);
        }
        n = nn; j0 = nj0; beg = nbeg; end = nend;
#pragma unroll
        for (int i = 0; i < 4; i++) { xc[i] = xn[i]; ec[i] = en[i]; }
    }
}

// ---------------------------------------------------------------------------
// GEMM (n1): 128x128 block tile, 256 threads, 8x8 microtile via f32x2.
// ---------------------------------------------------------------------------
__device__ __forceinline__ void gemm_chunk128(
    const float* __restrict__ A, const float* __restrict__ Aadd, int lda4,
    const float* __restrict__ W, int k0, int m0,
    float (*sA)[36], float (*sW)[128], u64 acc2[8][4], int tid)
{
    const float4* A4  = (const float4*)A;
    const float4* Aa4 = (const float4*)Aadd;
#pragma unroll
    for (int it = 0; it < 4; ++it) {
        int idx = it * 256 + tid;
        int r   = idx >> 3;
        int cq  = idx & 7;
        float4 v = make_float4(0.f, 0.f, 0.f, 0.f);
        int gr = m0 + r;
        if (gr < N_NODES) {
            v = A4[(size_t)gr * lda4 + (k0 >> 2) + cq];
            if (Aadd) {
                float4 u = Aa4[(size_t)gr * lda4 + (k0 >> 2) + cq];
                v.x += u.x; v.y += u.y; v.z += u.z; v.w += u.w;
            }
        }
        *(float4*)&sA[r][cq * 4] = v;
    }
    const float4* W4 = (const float4*)W;
#pragma unroll
    for (int it = 0; it < 4; ++it) {
        int idx = it * 256 + tid;
        int kr  = idx >> 5;
        int cq  = idx & 31;
        *(float4*)&sW[kr][cq * 4] = W4[(size_t)(k0 + kr) * 32 + cq];
    }
    __syncthreads();

    const int rg = (tid >> 4) * 8;
    const int cg = (tid & 15) * 8;
#pragma unroll
    for (int kk = 0; kk < 32; kk += 2) {
        ulonglong2 b0a = *(const ulonglong2*)&sW[kk][cg];
        ulonglong2 b0b = *(const ulonglong2*)&sW[kk][cg + 4];
        ulonglong2 b1a = *(const ulonglong2*)&sW[kk + 1][cg];
        ulonglong2 b1b = *(const ulonglong2*)&sW[kk + 1][cg + 4];
        u64 bv0[4] = { b0a.x, b0a.y, b0b.x, b0b.y };
        u64 bv1[4] = { b1a.x, b1a.y, b1b.x, b1b.y };
#pragma unroll
        for (int i = 0; i < 8; i++) {
            float2 a2 = *(const float2*)&sA[rg + i][kk];
            u64 aP0 = pack2(a2.x, a2.x);
            u64 aP1 = pack2(a2.y, a2.y);
#pragma unroll
            for (int jp = 0; jp < 4; jp++) {
                acc2[i][jp] = ffma2(aP0, bv0[jp], acc2[i][jp]);
                acc2[i][jp] = ffma2(aP1, bv1[jp], acc2[i][jp]);
            }
        }
    }
    __syncthreads();
}

__device__ __forceinline__ float gelu_exact(float v) {
    return 0.5f * v * (1.f + erff(v * 0.70710678118654752f));
}

// ---------------------------------------------------------------------------
// N1: t[dir] = 0.5 * gelu((x + agg[dir]) @ W1 + b1)   (ALPHA folded here)
// ---------------------------------------------------------------------------
__global__ __launch_bounds__(256, 2) void n1_kernel(
    const float* __restrict__ x,
    const float* __restrict__ W1_in,  const float* __restrict__ b1_in,
    const float* __restrict__ W1_out, const float* __restrict__ b1_out)
{
    const int dir = blockIdx.y;
    const float* W1 = dir ? W1_out : W1_in;
    const float* b1 = dir ? b1_out : b1_in;
    const float* agg = g_agg[dir];
    float* tptr = g_t[dir];

    __shared__ float sA[128][36];
    __shared__ float sW[32][128];
    u64 acc2[8][4];
#pragma unroll
    for (int i = 0; i < 8; i++)
#pragma unroll
        for (int j = 0; j < 4; j++) acc2[i][j] = 0ull;

    const int tid = threadIdx.x;
    const int m0  = blockIdx.x * 128;

    gemm_chunk128(x, agg, 16, W1,  0, m0, sA, sW, acc2, tid);
    gemm_chunk128(x, agg, 16, W1, 32, m0, sA, sW, acc2, tid);

    const int rg = (tid >> 4) * 8;
    const int cg = (tid & 15) * 8;
#pragma unroll
    for (int i = 0; i < 8; i++) {
        int gr = m0 + rg + i;
        if (gr < N_NODES) {
            float o[8];
#pragma unroll
            for (int jp = 0; jp < 4; jp++) {
                float lo, hi;
                unpack2(acc2[i][jp], lo, hi);
                o[2 * jp]     = 0.5f * gelu_exact(lo + b1[cg + 2 * jp]);
                o[2 * jp + 1] = 0.5f * gelu_exact(hi + b1[cg + 2 * jp + 1]);
            }
            *(float4*)&tptr[(size_t)gr * EMB + cg]     = *(float4*)&o[0];
            *(float4*)&tptr[(size_t)gr * EMB + cg + 4] = *(float4*)&o[4];
        }
    }
}

// ---------------------------------------------------------------------------
// N2: out = tS_out@W2_out + tS_in@W2_in + x@Wr + [0.5*(b2_out+b2_in)+br]
// cp.async double-buffered, K-chunk = 16, 20 chunks over 3 sources.
// ---------------------------------------------------------------------------
#define N2_CHUNKS 20

__global__ __launch_bounds__(256, 2) void n2_kernel(
    const float* __restrict__ x,
    const float* __restrict__ W2_in,  const float* __restrict__ b2_in,
    const float* __restrict__ W2_out, const float* __restrict__ b2_out,
    const float* __restrict__ Wr,     const float* __restrict__ br,
    float* __restrict__ out)
{
    __shared__ float sA[2][128][20];
    __shared__ float sW[2][16][128];
    u64 acc2[8][4];
#pragma unroll
    for (int i = 0; i < 8; i++)
#pragma unroll
        for (int j = 0; j < 4; j++) acc2[i][j] = 0ull;

    const int tid = threadIdx.x;
    const int m0  = blockIdx.x * 128;

    auto issue = [&](int c, int buf) {
        const float4* A4; int lda4, k4;
        const float4* W4;
        if (c < 8)       { A4 = (const float4*)g_t[1]; lda4 = 32; k4 = c * 4;
                           W4 = (const float4*)W2_out + (size_t)c * 16 * 32; }
        else if (c < 16) { A4 = (const float4*)g_t[0]; lda4 = 32; k4 = (c - 8) * 4;
                           W4 = (const float4*)W2_in + (size_t)(c - 8) * 16 * 32; }
        else             { A4 = (const float4*)x;      lda4 = 16; k4 = (c - 16) * 4;
                           W4 = (const float4*)Wr + (size_t)(c - 16) * 16 * 32; }
#pragma unroll
        for (int it = 0; it < 2; it++) {
            int idx = it * 256 + tid;        // 0..511 : A rows
            int r  = idx >> 2;
            int cq = idx & 3;
            int gr = m0 + r;
            if (gr < N_NODES)
                cp16(&sA[buf][r][cq * 4], A4 + (size_t)gr * lda4 + k4 + cq);
        }
#pragma unroll
        for (int it = 0; it < 2; it++) {
            int idx = it * 256 + tid;        // 0..511 : W 16x32 f4
            int kr = idx >> 5;
            int cq = idx & 31;
            cp16(&sW[buf][kr][cq * 4], W4 + kr * 32 + cq);
        }
        asm volatile("cp.async.commit_group;");
    };

    issue(0, 0);

    const int rg = (tid >> 4) * 8;
    const int cg = (tid & 15) * 8;

#pragma unroll 1
    for (int c = 0; c < N2_CHUNKS; c++) {
        const int buf = c & 1;
        if (c + 1 < N2_CHUNKS) {
            issue(c + 1, buf ^ 1);
            asm volatile("cp.async.wait_group 1;");
        } else {
            asm volatile("cp.async.wait_group 0;");
        }
        __syncthreads();

#pragma unroll
        for (int kk = 0; kk < 16; kk += 2) {
            ulonglong2 b0a = *(const ulonglong2*)&sW[buf][kk][cg];
            ulonglong2 b0b = *(const ulonglong2*)&sW[buf][kk][cg + 4];
            ulonglong2 b1a = *(const ulonglong2*)&sW[buf][kk + 1][cg];
            ulonglong2 b1b = *(const ulonglong2*)&sW[buf][kk + 1][cg + 4];
            u64 bv0[4] = { b0a.x, b0a.y, b0b.x, b0b.y };
            u64 bv1[4] = { b1a.x, b1a.y, b1b.x, b1b.y };
#pragma unroll
            for (int i = 0; i < 8; i++) {
                float2 a2 = *(const float2*)&sA[buf][rg + i][kk];
                u64 aP0 = pack2(a2.x, a2.x);
                u64 aP1 = pack2(a2.y, a2.y);
#pragma unroll
                for (int jp = 0; jp < 4; jp++) {
                    acc2[i][jp] = ffma2(aP0, bv0[jp], acc2[i][jp]);
                    acc2[i][jp] = ffma2(aP1, bv1[jp], acc2[i][jp]);
                }
            }
        }
        __syncthreads();
    }

#pragma unroll
    for (int i = 0; i < 8; i++) {
        int gr = m0 + rg + i;
        if (gr < N_NODES) {
            float o[8];
#pragma unroll
            for (int jp = 0; jp < 4; jp++) {
                float lo, hi;
                unpack2(acc2[i][jp], lo, hi);
                int c0 = cg + 2 * jp;
                o[2 * jp]     = lo + 0.5f * (b2_out[c0] + b2_in[c0]) + br[c0];
                o[2 * jp + 1] = hi + 0.5f * (b2_out[c0 + 1] + b2_in[c0 + 1]) + br[c0 + 1];
            }
            *(float4*)&out[(size_t)gr * EMB + cg]     = *(float4*)&o[0];
            *(float4*)&out[(size_t)gr * EMB + cg + 4] = *(float4*)&o[4];
        }
    }
}

// ---------------------------------------------------------------------------
// launch
// ---------------------------------------------------------------------------
extern "C" void kernel_launch(void* const* d_in, const int* in_sizes, int n_in,
                              void* d_out, int out_size)
{
    const float* x      = (const float*)d_in[0];
    const int*   ei     = (const int*)d_in[1];
    const float* ea     = (const float*)d_in[2];
    const float* We_in  = (const float*)d_in[3];
    const float* be_in  = (const float*)d_in[4];
    const float* W1_in  = (const float*)d_in[5];
    const float* b1_in  = (const float*)d_in[6];
    const float* W2_in  = (const float*)d_in[7];
    const float* b2_in  = (const float*)d_in[8];
    const float* We_out = (const float*)d_in[9];
    const float* be_out = (const float*)d_in[10];
    const float* W1_out = (const float*)d_in[11];
    const float* b1_out = (const float*)d_in[12];
    const float* W2_out = (const float*)d_in[13];
    const float* b2_out = (const float*)d_in[14];
    const float* Wr     = (const float*)d_in[15];
    const float* br     = (const float*)d_in[16];
    float* out = (float*)d_out;

    // ---- CSR build ----
    zero_deg_kernel<<<(N_NODES + 255) / 256, 256>>>();
    count_kernel<<<(N_EDGES + 255) / 256, 256>>>(ei);
    scan1_kernel<<<dim3(NBLK, 2), SCAN_BLK>>>();
    scan2_kernel<<<dim3(1, 2), 256>>>();
    scan3_kernel<<<dim3(NBLK, 2), SCAN_BLK>>>();
    fill_kernel<<<(N_EDGES + 255) / 256, 256>>>(ei);

    // ---- aggregation (atomic-free, f32x2, cross-node pipelined) ----
    agg_kernel<<<dim3(296, 2), 256>>>(
        (const float2*)x, ea,
        (const float2*)We_in,  (const float2*)be_in,
        (const float2*)We_out, (const float2*)be_out);

    // ---- node MLPs ----
    dim3 ngrid((N_NODES + 127) / 128, 2);
    n1_kernel<<<ngrid, 256>>>(x, W1_in, b1_in, W1_out, b1_out);

    n2_kernel<<<(N_NODES + 127) / 128, 256>>>(
        x, W2_in, b2_in, W2_out, b2_out, Wr, br, out);
}